// round 2
// baseline (speedup 1.0000x reference)
#include <cuda_runtime.h>
#include <cuda_bf16.h>
#include <cstdint>

// ---------------- problem dims ----------------
#define B_DIM 512
#define NIN   64
#define DIN   128
#define NOUT  64
#define DOUT  128
#define KSEL  4
#define YCOLS (NOUT * DOUT)        // 8192
#define YELEMS (B_DIM * YCOLS)     // 4194304
#define BN_EPS 1e-5f

#define KD      (KSEL * DIN)       // 512 (logical K per head)
#define NCHUNK  24                 // 3 splits x 4 k-sel x 2 half-DIN; 64 bf16 per chunk

// ---------------- scratch (device globals; no allocation allowed) ----------------
__device__ __align__(16) float          g_y[YELEMS];                 // 16.8 MB
__device__ __align__(16) __nv_bfloat16  g_xhi[B_DIM * NIN * DIN];    // 8.4 MB
__device__ __align__(16) __nv_bfloat16  g_xlo[B_DIM * NIN * DIN];
__device__ __align__(16) __nv_bfloat16  g_wthi[NOUT * DOUT * KD];    // [o][e][k*128+d]
__device__ __align__(16) __nv_bfloat16  g_wtlo[NOUT * DOUT * KD];
__device__ __align__(16) float          g_scale[YCOLS];
__device__ __align__(16) float          g_shift[YCOLS];

// ---------------- helpers ----------------
__device__ __forceinline__ uint32_t smem_u32(const void* p) {
    uint32_t a;
    asm("{ .reg .u64 t; cvta.to.shared.u64 t, %1; cvt.u32.u64 %0, t; }" : "=r"(a) : "l"(p));
    return a;
}
__device__ __forceinline__ void cp_async16(uint32_t dst, const void* src) {
    asm volatile("cp.async.cg.shared.global [%0], [%1], 16;" :: "r"(dst), "l"(src) : "memory");
}
__device__ __forceinline__ void cp_commit() {
    asm volatile("cp.async.commit_group;" ::: "memory");
}
template <int N>
__device__ __forceinline__ void cp_wait() {
    asm volatile("cp.async.wait_group %0;" :: "n"(N) : "memory");
}
__device__ __forceinline__ void ldsm_x4(uint32_t* r, uint32_t addr) {
    asm volatile("ldmatrix.sync.aligned.m8n8.x4.shared.b16 {%0,%1,%2,%3}, [%4];"
                 : "=r"(r[0]), "=r"(r[1]), "=r"(r[2]), "=r"(r[3]) : "r"(addr));
}
__device__ __forceinline__ void mma16816(float* d, const uint32_t* a, uint32_t b0, uint32_t b1) {
    asm volatile(
        "mma.sync.aligned.m16n8k16.row.col.f32.bf16.bf16.f32 "
        "{%0,%1,%2,%3}, {%4,%5,%6,%7}, {%8,%9}, {%0,%1,%2,%3};"
        : "+f"(d[0]), "+f"(d[1]), "+f"(d[2]), "+f"(d[3])
        : "r"(a[0]), "r"(a[1]), "r"(a[2]), "r"(a[3]), "r"(b0), "r"(b1));
}

// ---------------- kernel 1: split x -> bf16 hi/lo ----------------
__global__ void eb_split_x(const float* __restrict__ x) {
    int i = blockIdx.x * blockDim.x + threadIdx.x;          // over 1,048,576 float4s
    float4 v = reinterpret_cast<const float4*>(x)[i];
    __nv_bfloat16 h0 = __float2bfloat16(v.x);
    __nv_bfloat16 h1 = __float2bfloat16(v.y);
    __nv_bfloat16 h2 = __float2bfloat16(v.z);
    __nv_bfloat16 h3 = __float2bfloat16(v.w);
    __nv_bfloat16 l0 = __float2bfloat16(v.x - __bfloat162float(h0));
    __nv_bfloat16 l1 = __float2bfloat16(v.y - __bfloat162float(h1));
    __nv_bfloat16 l2 = __float2bfloat16(v.z - __bfloat162float(h2));
    __nv_bfloat16 l3 = __float2bfloat16(v.w - __bfloat162float(h3));
    uint2 ph, pl;
    ph.x = (uint32_t)__bfloat16_as_ushort(h0) | ((uint32_t)__bfloat16_as_ushort(h1) << 16);
    ph.y = (uint32_t)__bfloat16_as_ushort(h2) | ((uint32_t)__bfloat16_as_ushort(h3) << 16);
    pl.x = (uint32_t)__bfloat16_as_ushort(l0) | ((uint32_t)__bfloat16_as_ushort(l1) << 16);
    pl.y = (uint32_t)__bfloat16_as_ushort(l2) | ((uint32_t)__bfloat16_as_ushort(l3) << 16);
    reinterpret_cast<uint2*>(g_xhi)[i] = ph;
    reinterpret_cast<uint2*>(g_xlo)[i] = pl;
}

// ---------------- kernel 2: split + transpose W -> Wt[o][e][k*128+d] ----------------
__global__ void eb_split_w(const float* __restrict__ W) {
    __shared__ float tile[128][33];
    int ok = blockIdx.x;           // (o,k) pair: 256 blocks
    int o = ok >> 2, k = ok & 3;
    const float* src = W + (size_t)ok * (DIN * DOUT);   // W[o][k][d][e]
    int t = threadIdx.x;           // 256 threads
    for (int eb = 0; eb < 4; ++eb) {
        __syncthreads();
        #pragma unroll
        for (int it = 0; it < 16; ++it) {
            int flat = it * 256 + t;
            int d = flat >> 5, e2 = flat & 31;
            tile[d][e2] = src[d * DOUT + eb * 32 + e2];
        }
        __syncthreads();
        #pragma unroll
        for (int it = 0; it < 16; ++it) {
            int flat = it * 256 + t;
            int e2 = flat >> 7, d = flat & 127;
            float v = tile[d][e2];
            __nv_bfloat16 h = __float2bfloat16(v);
            __nv_bfloat16 l = __float2bfloat16(v - __bfloat162float(h));
            size_t off = (size_t)o * (DOUT * KD) + (size_t)(eb * 32 + e2) * KD + k * DIN + d;
            g_wthi[off] = h;
            g_wtlo[off] = l;
        }
    }
}

// ---------------- kernel 3: HMMA GEMM ----------------
// Per CTA: D(128x128) += A(128 x 1536) * B(1536 x 128)^T  for one (o, m-tile).
// K streamed as 24 chunks of 64 bf16 (=128B rows). 3-stage cp.async pipeline.
// smem stage: A tile 128x64 bf16 (16KB) + B tile 128x64 bf16 (16KB) = 32KB.
#define STAGE_BYTES 32768
#define GEMM_SMEM_BYTES (3 * STAGE_BYTES + 1024)

__global__ void __launch_bounds__(256, 2)
eb_gemm(const int* __restrict__ idx) {
    extern __shared__ char dsm[];
    uint32_t raw = smem_u32(dsm);
    uint32_t sbase = (raw + 1023u) & ~1023u;

    const int tid  = threadIdx.x;
    const int lane = tid & 31;
    const int wid  = tid >> 5;
    const int warp_m = wid & 3;          // 4 M-warps of 32 rows
    const int warp_n = wid >> 2;         // 2 N-warps of 64 cols
    const int o  = blockIdx.x >> 2;
    const int mt = blockIdx.x & 3;

    // gather indices for this head
    int nin[4];
    #pragma unroll
    for (int k = 0; k < 4; ++k) nin[k] = idx[(o << 2) + k];

    // ---- cp.async prefetch of one K-chunk (stage c) into buffer c%3 ----
    // chunk c: split s=c>>3 (0:hi*hi 1:hi*lo 2:lo*hi), k=(c&7)>>1, dh=c&1
    auto prefetch = [&](int c) {
        int s = c >> 3, rm = c & 7, k = rm >> 1, dh = rm & 1;
        const __nv_bfloat16* asrc = (s == 2) ? g_xlo  : g_xhi;
        const __nv_bfloat16* bsrc = (s == 1) ? g_wtlo : g_wthi;
        uint32_t abuf = sbase + (uint32_t)(c % 3) * STAGE_BYTES;
        uint32_t bbuf = abuf + 16384;
        const __nv_bfloat16* abase = asrc + ((size_t)(mt * 128) * NIN + nin[k]) * DIN + dh * 64;
        const __nv_bfloat16* bbase = bsrc + (size_t)o * (DOUT * KD) + k * DIN + dh * 64;
        #pragma unroll
        for (int it = 0; it < 4; ++it) {
            int v = it * 256 + tid;          // 1024 16B chunks per tile
            int row = v >> 3, cc = v & 7;
            uint32_t dsw = (uint32_t)row * 128 + (((uint32_t)cc * 16) ^ (((uint32_t)row & 7) << 4));
            cp_async16(abuf + dsw, abase + (size_t)row * (NIN * DIN) + cc * 8);
            cp_async16(bbuf + dsw, bbase + (size_t)row * KD + cc * 8);
        }
    };

    // ---- ldmatrix lane addressing (XOR-swizzled, conflict-free) ----
    const int sub = lane >> 3;
    const int rowA = warp_m * 32 + (sub & 1) * 8 + (lane & 7);
    const int khA  = sub >> 1;                       // k-half (0/1) for A
    const uint32_t swzA = ((uint32_t)rowA & 7) << 4;
    const int rowB = warp_n * 64 + (sub >> 1) * 8 + (lane & 7);
    const int khB  = sub & 1;                        // k-half (0/1) for B
    const uint32_t swzB = ((uint32_t)rowB & 7) << 4;

    float acc[2][8][4];
    #pragma unroll
    for (int mi = 0; mi < 2; ++mi)
        #pragma unroll
        for (int ni = 0; ni < 8; ++ni)
            #pragma unroll
            for (int q = 0; q < 4; ++q) acc[mi][ni][q] = 0.0f;

    prefetch(0); cp_commit();
    prefetch(1); cp_commit();

    for (int c = 0; c < NCHUNK; ++c) {
        cp_wait<1>();
        __syncthreads();
        if (c + 2 < NCHUNK) prefetch(c + 2);
        cp_commit();

        uint32_t abuf = sbase + (uint32_t)(c % 3) * STAGE_BYTES;
        uint32_t bbuf = abuf + 16384;
        #pragma unroll
        for (int ks = 0; ks < 4; ++ks) {
            uint32_t ka = (((uint32_t)ks * 32 + (uint32_t)khA * 16) ^ swzA);
            uint32_t kb = (((uint32_t)ks * 32 + (uint32_t)khB * 16) ^ swzB);
            uint32_t a[2][4];
            ldsm_x4(a[0], abuf + (uint32_t)rowA * 128 + ka);
            ldsm_x4(a[1], abuf + (uint32_t)(rowA + 16) * 128 + ka);
            uint32_t b[4][4];
            #pragma unroll
            for (int nb = 0; nb < 4; ++nb)
                ldsm_x4(b[nb], bbuf + (uint32_t)(rowB + nb * 16) * 128 + kb);
            #pragma unroll
            for (int mi = 0; mi < 2; ++mi)
                #pragma unroll
                for (int ni = 0; ni < 8; ++ni)
                    mma16816(acc[mi][ni], a[mi], b[ni >> 1][(ni & 1) * 2], b[ni >> 1][(ni & 1) * 2 + 1]);
        }
        __syncthreads();
    }

    // ---- epilogue: write fp32 accumulators to g_y ----
    // C frag m16n8: thread t -> (row lane/4, col 2*(lane%4)) and (row+8, col)
    const int r0 = mt * 128 + warp_m * 32 + (lane >> 2);
    const int col0 = o * DOUT + warp_n * 64 + (lane & 3) * 2;
    #pragma unroll
    for (int mi = 0; mi < 2; ++mi) {
        #pragma unroll
        for (int ni = 0; ni < 8; ++ni) {
            float* p0 = g_y + (size_t)(r0 + mi * 16) * YCOLS + col0 + ni * 8;
            float* p1 = p0 + 8 * YCOLS;
            *reinterpret_cast<float2*>(p0) = make_float2(acc[mi][ni][0], acc[mi][ni][1]);
            *reinterpret_cast<float2*>(p1) = make_float2(acc[mi][ni][2], acc[mi][ni][3]);
        }
    }
}

// ---------------- kernel 4: per-column batch stats -> scale/shift ----------------
__global__ void eb_stats(const float* __restrict__ gamma, const float* __restrict__ beta) {
    int j = blockIdx.x * blockDim.x + threadIdx.x;   // 8192 columns
    const float* p = g_y + j;
    float s0 = 0.f, s1 = 0.f, s2 = 0.f, s3 = 0.f;
    float q0 = 0.f, q1 = 0.f, q2 = 0.f, q3 = 0.f;
    #pragma unroll 4
    for (int r = 0; r < B_DIM; r += 4) {
        float a0 = p[(r + 0) * YCOLS];
        float a1 = p[(r + 1) * YCOLS];
        float a2 = p[(r + 2) * YCOLS];
        float a3 = p[(r + 3) * YCOLS];
        s0 += a0; q0 = fmaf(a0, a0, q0);
        s1 += a1; q1 = fmaf(a1, a1, q1);
        s2 += a2; q2 = fmaf(a2, a2, q2);
        s3 += a3; q3 = fmaf(a3, a3, q3);
    }
    float sum = (s0 + s1) + (s2 + s3);
    float sq  = (q0 + q1) + (q2 + q3);
    float inv = 1.0f / (float)B_DIM;
    float mean = sum * inv;
    float var  = fmaf(sq, inv, -mean * mean);
    float sc = gamma[j] * rsqrtf(var + BN_EPS);
    g_scale[j] = sc;
    g_shift[j] = fmaf(-mean, sc, beta[j]);
}

// ---------------- kernel 5: BN apply + SiLU ----------------
__global__ void eb_bn_silu(float* __restrict__ out) {
    int i = blockIdx.x * blockDim.x + threadIdx.x;   // over 1,048,576 float4s
    float4 v = reinterpret_cast<const float4*>(g_y)[i];
    int col = (i << 2) & (YCOLS - 1);
    float4 sc = *reinterpret_cast<const float4*>(g_scale + col);
    float4 sh = *reinterpret_cast<const float4*>(g_shift + col);
    float y0 = fmaf(v.x, sc.x, sh.x);
    float y1 = fmaf(v.y, sc.y, sh.y);
    float y2 = fmaf(v.z, sc.z, sh.z);
    float y3 = fmaf(v.w, sc.w, sh.w);
    float4 r;
    r.x = y0 / (1.0f + expf(-y0));
    r.y = y1 / (1.0f + expf(-y1));
    r.z = y2 / (1.0f + expf(-y2));
    r.w = y3 / (1.0f + expf(-y3));
    reinterpret_cast<float4*>(out)[i] = r;
}

// ---------------- launch ----------------
extern "C" void kernel_launch(void* const* d_in, const int* in_sizes, int n_in,
                              void* d_out, int out_size) {
    const float* x     = (const float*)d_in[0];   // (512,64,128)
    const float* W     = (const float*)d_in[1];   // (64,4,128,128)
    // d_in[2] = bias: provably cancelled by BatchNorm (batch-constant shift) — unused.
    const float* gamma = (const float*)d_in[3];   // (8192)
    const float* beta  = (const float*)d_in[4];   // (8192)
    const int*   idx   = (const int*)d_in[5];     // (64,4)
    float* out = (float*)d_out;

    cudaFuncSetAttribute(eb_gemm, cudaFuncAttributeMaxDynamicSharedMemorySize, GEMM_SMEM_BYTES);

    eb_split_x<<<4096, 256>>>(x);
    eb_split_w<<<256, 256>>>(W);
    eb_gemm<<<256, 256, GEMM_SMEM_BYTES>>>(idx);
    eb_stats<<<32, 256>>>(gamma, beta);
    eb_bn_silu<<<4096, 256>>>(out);
}

// round 3
// speedup vs baseline: 1.1589x; 1.1589x over previous
#include <cuda_runtime.h>
#include <cuda_bf16.h>
#include <cstdint>

// ---------------- problem dims ----------------
#define B_DIM 512
#define NIN   64
#define DIN   128
#define NOUT  64
#define DOUT  128
#define KSEL  4
#define YCOLS (NOUT * DOUT)        // 8192
#define YELEMS (B_DIM * YCOLS)     // 4194304
#define BN_EPS 1e-5f

#define KD      (KSEL * DIN)       // 512 (logical K per head)
#define NCHUNK  24                 // 3 splits x 4 k-sel x 2 half-DIN; 64 bf16 per chunk

#define NROWG   8                  // row groups for two-phase stats
#define ROWS_PER_G (B_DIM / NROWG) // 64

// ---------------- scratch (device globals; no allocation allowed) ----------------
__device__ __align__(16) float          g_y[YELEMS];                 // 16.8 MB
__device__ __align__(16) __nv_bfloat16  g_xhi[B_DIM * NIN * DIN];    // 8.4 MB
__device__ __align__(16) __nv_bfloat16  g_xlo[B_DIM * NIN * DIN];
__device__ __align__(16) __nv_bfloat16  g_wthi[NOUT * DOUT * KD];    // [o][e][k*128+d]
__device__ __align__(16) __nv_bfloat16  g_wtlo[NOUT * DOUT * KD];
__device__ __align__(16) float          g_scale[YCOLS];
__device__ __align__(16) float          g_shift[YCOLS];
__device__ __align__(16) float          g_psum[NROWG * YCOLS];       // 256 KB
__device__ __align__(16) float          g_psq [NROWG * YCOLS];       // 256 KB

// ---------------- helpers ----------------
__device__ __forceinline__ uint32_t smem_u32(const void* p) {
    uint32_t a;
    asm("{ .reg .u64 t; cvta.to.shared.u64 t, %1; cvt.u32.u64 %0, t; }" : "=r"(a) : "l"(p));
    return a;
}
__device__ __forceinline__ void cp_async16(uint32_t dst, const void* src) {
    asm volatile("cp.async.cg.shared.global [%0], [%1], 16;" :: "r"(dst), "l"(src) : "memory");
}
__device__ __forceinline__ void cp_commit() {
    asm volatile("cp.async.commit_group;" ::: "memory");
}
template <int N>
__device__ __forceinline__ void cp_wait() {
    asm volatile("cp.async.wait_group %0;" :: "n"(N) : "memory");
}
__device__ __forceinline__ void ldsm_x4(uint32_t* r, uint32_t addr) {
    asm volatile("ldmatrix.sync.aligned.m8n8.x4.shared.b16 {%0,%1,%2,%3}, [%4];"
                 : "=r"(r[0]), "=r"(r[1]), "=r"(r[2]), "=r"(r[3]) : "r"(addr));
}
__device__ __forceinline__ void mma16816(float* d, const uint32_t* a, uint32_t b0, uint32_t b1) {
    asm volatile(
        "mma.sync.aligned.m16n8k16.row.col.f32.bf16.bf16.f32 "
        "{%0,%1,%2,%3}, {%4,%5,%6,%7}, {%8,%9}, {%0,%1,%2,%3};"
        : "+f"(d[0]), "+f"(d[1]), "+f"(d[2]), "+f"(d[3])
        : "r"(a[0]), "r"(a[1]), "r"(a[2]), "r"(a[3]), "r"(b0), "r"(b1));
}

// ---------------- kernel 1: split x -> bf16 hi/lo ----------------
__global__ void eb_split_x(const float* __restrict__ x) {
    int i = blockIdx.x * blockDim.x + threadIdx.x;          // over 1,048,576 float4s
    float4 v = reinterpret_cast<const float4*>(x)[i];
    __nv_bfloat16 h0 = __float2bfloat16(v.x);
    __nv_bfloat16 h1 = __float2bfloat16(v.y);
    __nv_bfloat16 h2 = __float2bfloat16(v.z);
    __nv_bfloat16 h3 = __float2bfloat16(v.w);
    __nv_bfloat16 l0 = __float2bfloat16(v.x - __bfloat162float(h0));
    __nv_bfloat16 l1 = __float2bfloat16(v.y - __bfloat162float(h1));
    __nv_bfloat16 l2 = __float2bfloat16(v.z - __bfloat162float(h2));
    __nv_bfloat16 l3 = __float2bfloat16(v.w - __bfloat162float(h3));
    uint2 ph, pl;
    ph.x = (uint32_t)__bfloat16_as_ushort(h0) | ((uint32_t)__bfloat16_as_ushort(h1) << 16);
    ph.y = (uint32_t)__bfloat16_as_ushort(h2) | ((uint32_t)__bfloat16_as_ushort(h3) << 16);
    pl.x = (uint32_t)__bfloat16_as_ushort(l0) | ((uint32_t)__bfloat16_as_ushort(l1) << 16);
    pl.y = (uint32_t)__bfloat16_as_ushort(l2) | ((uint32_t)__bfloat16_as_ushort(l3) << 16);
    reinterpret_cast<uint2*>(g_xhi)[i] = ph;
    reinterpret_cast<uint2*>(g_xlo)[i] = pl;
}

// ---------------- kernel 2: split + transpose W -> Wt[o][e][k*128+d] ----------------
__global__ void eb_split_w(const float* __restrict__ W) {
    __shared__ float tile[128][33];
    int ok = blockIdx.x;           // (o,k) pair: 256 blocks
    int o = ok >> 2, k = ok & 3;
    const float* src = W + (size_t)ok * (DIN * DOUT);   // W[o][k][d][e]
    int t = threadIdx.x;           // 256 threads
    for (int eb = 0; eb < 4; ++eb) {
        __syncthreads();
        #pragma unroll
        for (int it = 0; it < 16; ++it) {
            int flat = it * 256 + t;
            int d = flat >> 5, e2 = flat & 31;
            tile[d][e2] = src[d * DOUT + eb * 32 + e2];
        }
        __syncthreads();
        #pragma unroll
        for (int it = 0; it < 16; ++it) {
            int flat = it * 256 + t;
            int e2 = flat >> 7, d = flat & 127;
            float v = tile[d][e2];
            __nv_bfloat16 h = __float2bfloat16(v);
            __nv_bfloat16 l = __float2bfloat16(v - __bfloat162float(h));
            size_t off = (size_t)o * (DOUT * KD) + (size_t)(eb * 32 + e2) * KD + k * DIN + d;
            g_wthi[off] = h;
            g_wtlo[off] = l;
        }
    }
}

// ---------------- kernel 3: HMMA GEMM ----------------
// Per CTA: D(128x128) += A(128 x 1536) * B(1536 x 128)^T  for one (o, m-tile).
// K streamed as 24 chunks of 64 bf16 (=128B rows). 3-stage cp.async pipeline.
#define STAGE_BYTES 32768
#define GEMM_SMEM_BYTES (3 * STAGE_BYTES + 1024)

__global__ void __launch_bounds__(256, 2)
eb_gemm(const int* __restrict__ idx) {
    extern __shared__ char dsm[];
    uint32_t raw = smem_u32(dsm);
    uint32_t sbase = (raw + 1023u) & ~1023u;

    const int tid  = threadIdx.x;
    const int lane = tid & 31;
    const int wid  = tid >> 5;
    const int warp_m = wid & 3;          // 4 M-warps of 32 rows
    const int warp_n = wid >> 2;         // 2 N-warps of 64 cols
    const int o  = blockIdx.x >> 2;
    const int mt = blockIdx.x & 3;

    int nin[4];
    #pragma unroll
    for (int k = 0; k < 4; ++k) nin[k] = idx[(o << 2) + k];

    auto prefetch = [&](int c) {
        int s = c >> 3, rm = c & 7, k = rm >> 1, dh = rm & 1;
        const __nv_bfloat16* asrc = (s == 2) ? g_xlo  : g_xhi;
        const __nv_bfloat16* bsrc = (s == 1) ? g_wtlo : g_wthi;
        uint32_t abuf = sbase + (uint32_t)(c % 3) * STAGE_BYTES;
        uint32_t bbuf = abuf + 16384;
        const __nv_bfloat16* abase = asrc + ((size_t)(mt * 128) * NIN + nin[k]) * DIN + dh * 64;
        const __nv_bfloat16* bbase = bsrc + (size_t)o * (DOUT * KD) + k * DIN + dh * 64;
        #pragma unroll
        for (int it = 0; it < 4; ++it) {
            int v = it * 256 + tid;          // 1024 16B chunks per tile
            int row = v >> 3, cc = v & 7;
            uint32_t dsw = (uint32_t)row * 128 + (((uint32_t)cc * 16) ^ (((uint32_t)row & 7) << 4));
            cp_async16(abuf + dsw, abase + (size_t)row * (NIN * DIN) + cc * 8);
            cp_async16(bbuf + dsw, bbase + (size_t)row * KD + cc * 8);
        }
    };

    const int sub = lane >> 3;
    const int rowA = warp_m * 32 + (sub & 1) * 8 + (lane & 7);
    const int khA  = sub >> 1;
    const uint32_t swzA = ((uint32_t)rowA & 7) << 4;
    const int rowB = warp_n * 64 + (sub >> 1) * 8 + (lane & 7);
    const int khB  = sub & 1;
    const uint32_t swzB = ((uint32_t)rowB & 7) << 4;

    float acc[2][8][4];
    #pragma unroll
    for (int mi = 0; mi < 2; ++mi)
        #pragma unroll
        for (int ni = 0; ni < 8; ++ni)
            #pragma unroll
            for (int q = 0; q < 4; ++q) acc[mi][ni][q] = 0.0f;

    prefetch(0); cp_commit();
    prefetch(1); cp_commit();

    for (int c = 0; c < NCHUNK; ++c) {
        cp_wait<1>();
        __syncthreads();
        if (c + 2 < NCHUNK) prefetch(c + 2);
        cp_commit();

        uint32_t abuf = sbase + (uint32_t)(c % 3) * STAGE_BYTES;
        uint32_t bbuf = abuf + 16384;
        #pragma unroll
        for (int ks = 0; ks < 4; ++ks) {
            uint32_t ka = (((uint32_t)ks * 32 + (uint32_t)khA * 16) ^ swzA);
            uint32_t kb = (((uint32_t)ks * 32 + (uint32_t)khB * 16) ^ swzB);
            uint32_t a[2][4];
            ldsm_x4(a[0], abuf + (uint32_t)rowA * 128 + ka);
            ldsm_x4(a[1], abuf + (uint32_t)(rowA + 16) * 128 + ka);
            uint32_t b[4][4];
            #pragma unroll
            for (int nb = 0; nb < 4; ++nb)
                ldsm_x4(b[nb], bbuf + (uint32_t)(rowB + nb * 16) * 128 + kb);
            #pragma unroll
            for (int mi = 0; mi < 2; ++mi)
                #pragma unroll
                for (int ni = 0; ni < 8; ++ni)
                    mma16816(acc[mi][ni], a[mi], b[ni >> 1][(ni & 1) * 2], b[ni >> 1][(ni & 1) * 2 + 1]);
        }
        __syncthreads();
    }

    const int r0 = mt * 128 + warp_m * 32 + (lane >> 2);
    const int col0 = o * DOUT + warp_n * 64 + (lane & 3) * 2;
    #pragma unroll
    for (int mi = 0; mi < 2; ++mi) {
        #pragma unroll
        for (int ni = 0; ni < 8; ++ni) {
            float* p0 = g_y + (size_t)(r0 + mi * 16) * YCOLS + col0 + ni * 8;
            float* p1 = p0 + 8 * YCOLS;
            *reinterpret_cast<float2*>(p0) = make_float2(acc[mi][ni][0], acc[mi][ni][1]);
            *reinterpret_cast<float2*>(p1) = make_float2(acc[mi][ni][2], acc[mi][ni][3]);
        }
    }
}

// ---------------- kernel 4a: partial per-column sums (row-group parallel) ----------------
__global__ void __launch_bounds__(256) eb_stats1() {
    int j  = blockIdx.x * 256 + threadIdx.x;      // column
    int rg = blockIdx.y;                          // row group
    const float* p = g_y + (size_t)rg * ROWS_PER_G * YCOLS + j;
    float s0 = 0.f, s1 = 0.f, s2 = 0.f, s3 = 0.f;
    float q0 = 0.f, q1 = 0.f, q2 = 0.f, q3 = 0.f;
    #pragma unroll 4
    for (int r = 0; r < ROWS_PER_G; r += 4) {
        float a0 = p[(r + 0) * YCOLS];
        float a1 = p[(r + 1) * YCOLS];
        float a2 = p[(r + 2) * YCOLS];
        float a3 = p[(r + 3) * YCOLS];
        s0 += a0; q0 = fmaf(a0, a0, q0);
        s1 += a1; q1 = fmaf(a1, a1, q1);
        s2 += a2; q2 = fmaf(a2, a2, q2);
        s3 += a3; q3 = fmaf(a3, a3, q3);
    }
    g_psum[rg * YCOLS + j] = (s0 + s1) + (s2 + s3);
    g_psq [rg * YCOLS + j] = (q0 + q1) + (q2 + q3);
}

// ---------------- kernel 4b: finalize scale/shift ----------------
__global__ void __launch_bounds__(256) eb_stats2(const float* __restrict__ gamma,
                                                 const float* __restrict__ beta) {
    int j = blockIdx.x * 256 + threadIdx.x;       // 8192 columns
    float sum = 0.f, sq = 0.f;
    #pragma unroll
    for (int rg = 0; rg < NROWG; ++rg) {
        sum += g_psum[rg * YCOLS + j];
        sq  += g_psq [rg * YCOLS + j];
    }
    float inv = 1.0f / (float)B_DIM;
    float mean = sum * inv;
    float var  = fmaf(sq, inv, -mean * mean);
    float sc = gamma[j] * rsqrtf(var + BN_EPS);
    g_scale[j] = sc;
    g_shift[j] = fmaf(-mean, sc, beta[j]);
}

// ---------------- kernel 5: BN apply + SiLU ----------------
__global__ void eb_bn_silu(float* __restrict__ out) {
    int i = blockIdx.x * blockDim.x + threadIdx.x;   // over 1,048,576 float4s
    float4 v = reinterpret_cast<const float4*>(g_y)[i];
    int col = (i << 2) & (YCOLS - 1);
    float4 sc = *reinterpret_cast<const float4*>(g_scale + col);
    float4 sh = *reinterpret_cast<const float4*>(g_shift + col);
    float y0 = fmaf(v.x, sc.x, sh.x);
    float y1 = fmaf(v.y, sc.y, sh.y);
    float y2 = fmaf(v.z, sc.z, sh.z);
    float y3 = fmaf(v.w, sc.w, sh.w);
    float4 r;
    r.x = y0 / (1.0f + expf(-y0));
    r.y = y1 / (1.0f + expf(-y1));
    r.z = y2 / (1.0f + expf(-y2));
    r.w = y3 / (1.0f + expf(-y3));
    reinterpret_cast<float4*>(out)[i] = r;
}

// ---------------- launch ----------------
extern "C" void kernel_launch(void* const* d_in, const int* in_sizes, int n_in,
                              void* d_out, int out_size) {
    const float* x     = (const float*)d_in[0];   // (512,64,128)
    const float* W     = (const float*)d_in[1];   // (64,4,128,128)
    // d_in[2] = bias: provably cancelled by BatchNorm (batch-constant shift) — unused.
    const float* gamma = (const float*)d_in[3];   // (8192)
    const float* beta  = (const float*)d_in[4];   // (8192)
    const int*   idx   = (const int*)d_in[5];     // (64,4)
    float* out = (float*)d_out;

    cudaFuncSetAttribute(eb_gemm, cudaFuncAttributeMaxDynamicSharedMemorySize, GEMM_SMEM_BYTES);

    eb_split_x<<<4096, 256>>>(x);
    eb_split_w<<<256, 256>>>(W);
    eb_gemm<<<256, 256, GEMM_SMEM_BYTES>>>(idx);
    eb_stats1<<<dim3(32, NROWG), 256>>>();
    eb_stats2<<<32, 256>>>(gamma, beta);
    eb_bn_silu<<<4096, 256>>>(out);
}